// round 14
// baseline (speedup 1.0000x reference)
#include <cuda_runtime.h>

#define LOG2E 1.4426950408889634f
#define NI 12                 // intervals per attention
#define NNODE 9               // Chebyshev nodes per interval (degree 8)
#define NODES (NI * NNODE)    // 108
#define NGRP 6                // node-groups for fused node eval (18 nodes each)

#define PROJ_KC 24            // 768 / 32
#define PROJ_KCH 32
#define MLP_KC 120            // 3840 / 32
#define MLP_KCH 32

// Kernel A block map: [0,64) pre-heavy, [64,96) copy, [96,288) fat-node,
// [288,360) proj (task = (bid-288)/24).
#define A_PRE_BLOCKS 96
#define A_NODE0 96
#define A_PROJ0 288
#define A_BLOCKS 360

// ---------------- scratch (__device__ globals; allocation-free rule) -------
__device__ float  g_fused[32 * 2304];            // [sentence | scene | speaker]
__device__ float  g_h_part[MLP_KC * 32 * 256];   // mlp1 partials [kc][b][j]
__device__ float  g_pp[3 * PROJ_KC * 32 * 512];  // proj partials [task][kc][b][j]
__device__ float2 g_nodes[32 * NODES];           // fused node table [b][m]
__device__ float  g_frange[32 * 2];              // fused range [b][min,max]
__device__ unsigned g_cntA = 0;                  // pre-done arrivals (reset by B)
__device__ unsigned g_cntB = 0;                  // mlp1-done arrivals (reset by A)

__constant__ float CHEB[9] = {1.f, 0.92387953f, 0.70710678f, 0.38268343f, 0.f,
                              -0.38268343f, -0.70710678f, -0.92387953f, -1.f};
__constant__ float LAMB[9] = {0.5f, -1.f, 1.f, -1.f, 1.f, -1.f, 1.f, -1.f, 0.5f};

__device__ __forceinline__ float ex2f(float x) {
    float y; asm("ex2.approx.f32 %0, %1;" : "=f"(y) : "f"(x)); return y;
}
__device__ __forceinline__ float wredsum(float v) {
#pragma unroll
    for (int o = 16; o > 0; o >>= 1) v += __shfl_xor_sync(0xffffffffu, v, o);
    return v;
}

// Gate: block-level wait until counter reaches target (producers co-resident
// in wave 1 by construction -> no deadlock).
__device__ __forceinline__ void gate_wait(unsigned* cnt, unsigned target) {
    if (threadIdx.x == 0) {
        while (*(volatile unsigned*)cnt < target) { __nanosleep(32); }
    }
    __syncthreads();
    __threadfence();
}
__device__ __forceinline__ void gate_arrive(unsigned* cnt) {
    __syncthreads();
    if (threadIdx.x == 0) { __threadfence(); atomicAdd(cnt, 1u); }
}

__device__ __forceinline__ float interp_s(float x, float xmin, float w, float hw,
                                          float invw,
                                          const float* __restrict__ snum,
                                          const float* __restrict__ sden) {
    int c = (int)((x - xmin) * invw);
    c = (c < 0) ? 0 : ((c >= NI) ? NI - 1 : c);
    const float x0 = xmin + (c + 0.5f) * w;
    const int base = c * NNODE;
    float wn = 0.f, wd = 0.f, hitn = 0.f, hitd = 1.f;
    bool hit = false;
#pragma unroll
    for (int m = 0; m < NNODE; m++) {
        float d = x - (x0 + hw * CHEB[m]);
        if (fabsf(d) < 1e-10f) { hit = true; hitn = snum[base + m]; hitd = sden[base + m]; d = 1.f; }
        float wm = __fdividef(LAMB[m], d);
        wn = fmaf(wm, snum[base + m], wn);
        wd = fmaf(wm, sden[base + m], wd);
    }
    return hit ? __fdividef(hitn, hitd) : __fdividef(wn, wd);
}

__device__ __forceinline__ float interp_g(float x, float xmin, float w, float hw,
                                          float invw,
                                          const float2* __restrict__ nodes) {
    int c = (int)((x - xmin) * invw);
    c = (c < 0) ? 0 : ((c >= NI) ? NI - 1 : c);
    const float x0 = xmin + (c + 0.5f) * w;
    const float2* nb = nodes + c * NNODE;
    float wn = 0.f, wd = 0.f, hitn = 0.f, hitd = 1.f;
    bool hit = false;
#pragma unroll
    for (int m = 0; m < NNODE; m++) {
        float2 nd = nb[m];
        float d = x - (x0 + hw * CHEB[m]);
        if (fabsf(d) < 1e-10f) { hit = true; hitn = nd.x; hitd = nd.y; d = 1.f; }
        float wm = __fdividef(LAMB[m], d);
        wn = fmaf(wm, nd.x, wn);
        wd = fmaf(wm, nd.y, wd);
    }
    return hit ? __fdividef(hitn, hitd) : __fdividef(wn, wd);
}

// ---------------------------------------------------------------------------
// Kernel A: pre-attentions (producers) + fused node table + projections
// (consumers), one launch, ticket-gated. grid 360, block 512.
// ---------------------------------------------------------------------------
__global__ void __launch_bounds__(512) kernelA(const float* __restrict__ sent,
                                               const float* __restrict__ ts,
                                               const float* __restrict__ oth,
                                               const float* __restrict__ sd,
                                               const float* __restrict__ ss,
                                               const float* __restrict__ Wsh) {
    const int bx = blockIdx.x;
    const int tid = threadIdx.x, lane = tid & 31, wid = tid >> 5;

    if (bx == 0 && tid == 0) atomicExch(&g_cntB, 0u);   // reset B's counter (prev replay done)

    __shared__ __align__(16) union SM {
        struct { float sq[768], sk[768], sv[768], snum[NODES], sden[NODES], red[32]; } h;
        struct { float sf[2304], red[16]; } n;
        struct { float xs[PROJ_KCH][36]; } p;
    } sm;

    if (bx < 64) {
        // ---- pre heavy (R9 code, 512 thr) ----
        const int b = bx & 31, task = bx >> 5;
        const float* q = (task == 0) ? oth : ss;
        const float* k = (task == 0) ? ts  : ss;
        const float* v = (task == 0) ? ts  : sd;
        const int outoff = (task == 0) ? 1536 : 768;

        for (int i = tid; i < 768; i += 512) {
            sm.h.sq[i] = q[b * 768 + i];
            sm.h.sk[i] = k[b * 768 + i];
            sm.h.sv[i] = v[b * 768 + i];
        }
        __syncthreads();

        float lmin = 1e30f, lmax = -1e30f;
        for (int i = tid; i < 768; i += 512) {
            float x = sm.h.sq[i];
            lmin = fminf(lmin, x); lmax = fmaxf(lmax, x);
        }
#pragma unroll
        for (int o = 16; o > 0; o >>= 1) {
            lmin = fminf(lmin, __shfl_xor_sync(0xffffffffu, lmin, o));
            lmax = fmaxf(lmax, __shfl_xor_sync(0xffffffffu, lmax, o));
        }
        if (lane == 0) { sm.h.red[wid] = lmin; sm.h.red[16 + wid] = lmax; }
        __syncthreads();
        float xmin = sm.h.red[0], xmax = sm.h.red[16];
#pragma unroll
        for (int i = 1; i < 16; i++) {
            xmin = fminf(xmin, sm.h.red[i]); xmax = fmaxf(xmax, sm.h.red[16 + i]);
        }

        const float w  = (xmax - xmin) * (1.f / NI);
        const float hw = 0.5f * w;

        for (int m = wid; m < NODES; m += 16) {
            const int c = m / NNODE, mm = m - c * NNODE;
            const float Xl = (xmin + (c + 0.5f) * w + hw * CHEB[mm]) * LOG2E;
            float sn = 0.f, sd_ = 0.f;
            for (int t = lane; t < 768; t += 32) {
                float e = ex2f(Xl * sm.h.sk[t]);
                sd_ += e;
                sn = fmaf(e, sm.h.sv[t], sn);
            }
            sn = wredsum(sn); sd_ = wredsum(sd_);
            if (lane == 0) { sm.h.snum[m] = sn; sm.h.sden[m] = sd_; }
        }
        __syncthreads();

        const float invw = __fdividef(1.f, w);
        for (int s = tid; s < 768; s += 512)
            g_fused[b * 2304 + outoff + s] =
                interp_s(sm.h.sq[s], xmin, w, hw, invw, sm.h.snum, sm.h.sden);

        gate_arrive(&g_cntA);
        return;
    }

    if (bx < A_PRE_BLOCKS) {
        // ---- sentence copy ----
        const int b = bx - 64;
        for (int i = tid; i < 768; i += 512) g_fused[b * 2304 + i] = sent[b * 768 + i];
        gate_arrive(&g_cntA);
        return;
    }

    if (bx < A_PROJ0) {
        // ---- fused node eval (consumer) ----
        const int idx = bx - A_NODE0;
        const int b = idx & 31, grp = idx >> 5;

        gate_wait(&g_cntA, A_PRE_BLOCKS);

        for (int i = tid; i < 576; i += 512)
            *reinterpret_cast<float4*>(sm.n.sf + i * 4) =
                *reinterpret_cast<const float4*>(g_fused + b * 2304 + i * 4);
        __syncthreads();

        float lmin = 1e30f, lmax = -1e30f;
        for (int i = tid; i < 2304; i += 512) {
            float x = sm.n.sf[i];
            lmin = fminf(lmin, x); lmax = fmaxf(lmax, x);
        }
#pragma unroll
        for (int o = 16; o > 0; o >>= 1) {
            lmin = fminf(lmin, __shfl_xor_sync(0xffffffffu, lmin, o));
            lmax = fmaxf(lmax, __shfl_xor_sync(0xffffffffu, lmax, o));
        }
        __shared__ float redn[32];
        if (lane == 0) { redn[wid] = lmin; redn[16 + wid] = lmax; }
        __syncthreads();
        float xmin = redn[0], xmax = redn[16];
#pragma unroll
        for (int i = 1; i < 16; i++) {
            xmin = fminf(xmin, redn[i]); xmax = fmaxf(xmax, redn[16 + i]);
        }

        if (grp == 0 && tid == 0) { g_frange[b * 2] = xmin; g_frange[b * 2 + 1] = xmax; }

        const float w  = (xmax - xmin) * (1.f / NI);
        const float hw = 0.5f * w;
        const int m0 = grp * (NODES / NGRP);

        for (int m = m0 + wid; m < m0 + NODES / NGRP; m += 16) {
            const int c = m / NNODE, mm = m - c * NNODE;
            const float Xl = (xmin + (c + 0.5f) * w + hw * CHEB[mm]) * LOG2E;
            float sn = 0.f, sd_ = 0.f;
            for (int t = lane; t < 2304; t += 32) {
                float f = sm.n.sf[t];
                float e = ex2f(Xl * f);
                sd_ += e;
                sn = fmaf(e, f, sn);     // v == f
            }
            sn = wredsum(sn); sd_ = wredsum(sd_);
            if (lane == 0) g_nodes[b * NODES + m] = make_float2(sn, sd_);
        }
        return;
    }

    // ---- proj split-K (task 0 = no wait; tasks 1,2 consume g_fused) ----
    const int p    = bx - A_PROJ0;          // 0..71
    const int task = p / PROJ_KC;
    const int kc   = p - task * PROJ_KC;
    const int j    = tid;                    // 0..511
    const int i0   = kc * PROJ_KCH;

    if (task != 0) gate_wait(&g_cntA, A_PRE_BLOCKS);

    for (int e = tid; e < PROJ_KCH * 32; e += 512) {
        int i = e & 31, b = e >> 5;
        sm.p.xs[i][b] = (task == 0) ? sent[b * 768 + i0 + i]
                                    : g_fused[b * 2304 + 768 * task + i0 + i];
    }
    __syncthreads();

    float acc[32];
#pragma unroll
    for (int b = 0; b < 32; b++) acc[b] = 0.f;

#pragma unroll
    for (int i = 0; i < PROJ_KCH; i++) {
        float wv = Wsh[(i0 + i) * 512 + j];
#pragma unroll
        for (int b4 = 0; b4 < 8; b4++) {
            float4 x = *reinterpret_cast<const float4*>(&sm.p.xs[i][b4 * 4]);
            acc[b4 * 4 + 0] = fmaf(x.x, wv, acc[b4 * 4 + 0]);
            acc[b4 * 4 + 1] = fmaf(x.y, wv, acc[b4 * 4 + 1]);
            acc[b4 * 4 + 2] = fmaf(x.z, wv, acc[b4 * 4 + 2]);
            acc[b4 * 4 + 3] = fmaf(x.w, wv, acc[b4 * 4 + 3]);
        }
    }

#pragma unroll
    for (int b = 0; b < 32; b++)
        g_pp[(((size_t)task * PROJ_KC + kc) * 32 + b) * 512 + j] = acc[b];
}

// ---------------------------------------------------------------------------
// Kernel B: mlp1 (120 blocks) + ticket-gated tail on blocks 0..31.
// grid 120, block 256.
// ---------------------------------------------------------------------------
__global__ void __launch_bounds__(256) kernelB(const float* __restrict__ W1,
                                               const float* __restrict__ bsh,
                                               const float* __restrict__ b1,
                                               const float* __restrict__ W2,
                                               const float* __restrict__ b2,
                                               float* __restrict__ out) {
    const int kc = blockIdx.x;
    const int i0 = kc * MLP_KCH;
    const int j  = threadIdx.x;

    if (kc == 0 && j == 0) atomicExch(&g_cntA, 0u);   // reset A's counter (A fully done)

    __shared__ __align__(16) float xs[MLP_KCH][36];

    if (kc < 72) {
        for (int e = threadIdx.x; e < MLP_KCH * 32; e += 256) {
            int ii = e & 31, b = e >> 5;
            const float xmin = g_frange[b * 2], xmax = g_frange[b * 2 + 1];
            const float w  = (xmax - xmin) * (1.f / NI);
            const float hw = 0.5f * w;
            const float invw = __fdividef(1.f, w);
            const float x = g_fused[b * 2304 + i0 + ii];
            xs[ii][b] = interp_g(x, xmin, w, hw, invw, g_nodes + b * NODES);
        }
    } else {
        const int t0   = i0 - 2304;
        const int task = t0 >> 9;
        const int jj0  = t0 & 511;
        for (int e = threadIdx.x; e < MLP_KCH * 32; e += 256) {
            int jl = e & 31, b = e >> 5;
            const int jj = jj0 + jl;
            float a = bsh[jj];
            const float* pp = g_pp + (((size_t)task * PROJ_KC) * 32 + b) * 512 + jj;
#pragma unroll
            for (int s = 0; s < PROJ_KC; s++) a += pp[(size_t)s * 32 * 512];
            xs[jl][b] = a;
        }
    }
    __syncthreads();

    float acc[32];
#pragma unroll
    for (int b = 0; b < 32; b++) acc[b] = 0.f;

#pragma unroll
    for (int i = 0; i < MLP_KCH; i++) {
        float w = W1[(i0 + i) * 256 + j];
#pragma unroll
        for (int b4 = 0; b4 < 8; b4++) {
            float4 x = *reinterpret_cast<const float4*>(&xs[i][b4 * 4]);
            acc[b4 * 4 + 0] = fmaf(x.x, w, acc[b4 * 4 + 0]);
            acc[b4 * 4 + 1] = fmaf(x.y, w, acc[b4 * 4 + 1]);
            acc[b4 * 4 + 2] = fmaf(x.z, w, acc[b4 * 4 + 2]);
            acc[b4 * 4 + 3] = fmaf(x.w, w, acc[b4 * 4 + 3]);
        }
    }

#pragma unroll
    for (int b = 0; b < 32; b++)
        g_h_part[((size_t)kc * 32 + b) * 256 + j] = acc[b];

    gate_arrive(&g_cntB);

    // ---- tail: blocks 0..31 (all 120 blocks co-resident -> safe spin) ----
    if (kc < 32) {
        gate_wait(&g_cntB, MLP_KC);

        const int b  = kc;
        const int j4 = threadIdx.x & 63;   // float4 column
        const int qt = threadIdx.x >> 6;   // kc-group 0..3 (30 each)

        __shared__ __align__(16) float4 sred[4][64];
        __shared__ __align__(16) float h[256];

        const float4* src = reinterpret_cast<const float4*>(g_h_part);
        float4 a = make_float4(0.f, 0.f, 0.f, 0.f);
#pragma unroll 6
        for (int s = 0; s < 30; s++) {
            const int kk = qt * 30 + s;
            float4 p = src[((size_t)kk * 32 + b) * 64 + j4];
            a.x += p.x; a.y += p.y; a.z += p.z; a.w += p.w;
        }
        sred[qt][j4] = a;
        __syncthreads();

        if (threadIdx.x < 64) {
            float4 t = sred[0][threadIdx.x];
#pragma unroll
            for (int s = 1; s < 4; s++) {
                float4 p = sred[s][threadIdx.x];
                t.x += p.x; t.y += p.y; t.z += p.z; t.w += p.w;
            }
            float4 bb = reinterpret_cast<const float4*>(b1)[threadIdx.x];
            float4 hv;
            hv.x = fmaxf(t.x + bb.x, 0.f);
            hv.y = fmaxf(t.y + bb.y, 0.f);
            hv.z = fmaxf(t.z + bb.z, 0.f);
            hv.w = fmaxf(t.w + bb.w, 0.f);
            *reinterpret_cast<float4*>(h + threadIdx.x * 4) = hv;
        }
        __syncthreads();

        const int w = threadIdx.x >> 5, lane = threadIdx.x & 31;
        if (w < 7) {
            float s = 0.f;
#pragma unroll
            for (int q = 0; q < 8; q++)
                s = fmaf(h[q * 32 + lane], W2[(q * 32 + lane) * 7 + w], s);
#pragma unroll
            for (int o = 16; o > 0; o >>= 1) s += __shfl_xor_sync(0xffffffffu, s, o);
            if (lane == 0) out[b * 7 + w] = 1.f / (1.f + __expf(-(s + b2[w])));
        }
    }
}

extern "C" void kernel_launch(void* const* d_in, const int* in_sizes, int n_in,
                              void* d_out, int out_size) {
    const float* sent = (const float*)d_in[0];
    const float* ts   = (const float*)d_in[1];
    const float* oth  = (const float*)d_in[2];
    const float* sd   = (const float*)d_in[3];
    const float* ss   = (const float*)d_in[4];
    const float* Wsh  = (const float*)d_in[5];
    const float* bsh  = (const float*)d_in[6];
    const float* W1   = (const float*)d_in[7];
    const float* b1   = (const float*)d_in[8];
    const float* W2   = (const float*)d_in[9];
    const float* b2   = (const float*)d_in[10];
    float* out = (float*)d_out;

    kernelA<<<A_BLOCKS, 512>>>(sent, ts, oth, sd, ss, Wsh);
    kernelB<<<MLP_KC, 256>>>(W1, bsh, b1, W2, b2, out);
}

// round 15
// speedup vs baseline: 1.1166x; 1.1166x over previous
#include <cuda_runtime.h>

#define LOG2E 1.4426950408889634f
#define NI 8                  // intervals per attention
#define NNODE 9               // Chebyshev nodes per interval (degree 8)
#define NODES (NI * NNODE)    // 72
#define NGRP 9                // node-groups for fused node eval (8 nodes each)

#define PROJ_KC 24            // 768 / 32
#define PROJ_KCH 32
#define MLP_KC 120            // 3840 / 32
#define MLP_KCH 32

#define FAT_NODE_BLOCKS (NGRP * 32)            // 288
#define FAT_PROJ_BLOCKS (PROJ_KC * 2 * 3)      // 144

// ---------------- scratch (__device__ globals; allocation-free rule) -------
__device__ float  g_fused[32 * 2304];            // [sentence | scene | speaker]
__device__ float  g_h_part[MLP_KC * 32 * 256];   // mlp1 partials [kc][b][j]
__device__ float  g_pp[3 * PROJ_KC * 32 * 512];  // proj partials [task][kc][b][j]
__device__ float2 g_nodes[32 * NODES];           // fused node table [b][m] (num,den)
__device__ float  g_frange[32 * 2];              // fused range [b][min,max]

__constant__ float CHEB[9] = {1.f, 0.92387953f, 0.70710678f, 0.38268343f, 0.f,
                              -0.38268343f, -0.70710678f, -0.92387953f, -1.f};
__constant__ float LAMB[9] = {0.5f, -1.f, 1.f, -1.f, 1.f, -1.f, 1.f, -1.f, 0.5f};

__device__ __forceinline__ float ex2f(float x) {
    float y; asm("ex2.approx.f32 %0, %1;" : "=f"(y) : "f"(x)); return y;
}
__device__ __forceinline__ float wredsum(float v) {
#pragma unroll
    for (int o = 16; o > 0; o >>= 1) v += __shfl_xor_sync(0xffffffffu, v, o);
    return v;
}

__device__ __forceinline__ float interp_s(float x, float xmin, float w, float hw,
                                          float invw,
                                          const float* __restrict__ snum,
                                          const float* __restrict__ sden) {
    int c = (int)((x - xmin) * invw);
    c = (c < 0) ? 0 : ((c >= NI) ? NI - 1 : c);
    const float x0 = xmin + (c + 0.5f) * w;
    const int base = c * NNODE;
    float wn = 0.f, wd = 0.f, hitn = 0.f, hitd = 1.f;
    bool hit = false;
#pragma unroll
    for (int m = 0; m < NNODE; m++) {
        float d = x - (x0 + hw * CHEB[m]);
        if (fabsf(d) < 1e-10f) { hit = true; hitn = snum[base + m]; hitd = sden[base + m]; d = 1.f; }
        float wm = __fdividef(LAMB[m], d);
        wn = fmaf(wm, snum[base + m], wn);
        wd = fmaf(wm, sden[base + m], wd);
    }
    return hit ? __fdividef(hitn, hitd) : __fdividef(wn, wd);
}

__device__ __forceinline__ float interp_g(float x, float xmin, float w, float hw,
                                          float invw,
                                          const float2* __restrict__ nodes) {
    int c = (int)((x - xmin) * invw);
    c = (c < 0) ? 0 : ((c >= NI) ? NI - 1 : c);
    const float x0 = xmin + (c + 0.5f) * w;
    const float2* nb = nodes + c * NNODE;
    float wn = 0.f, wd = 0.f, hitn = 0.f, hitd = 1.f;
    bool hit = false;
#pragma unroll
    for (int m = 0; m < NNODE; m++) {
        float2 nd = nb[m];
        float d = x - (x0 + hw * CHEB[m]);
        if (fabsf(d) < 1e-10f) { hit = true; hitn = nd.x; hitd = nd.y; d = 1.f; }
        float wm = __fdividef(LAMB[m], d);
        wn = fmaf(wm, nd.x, wn);
        wd = fmaf(wm, nd.y, wd);
    }
    return hit ? __fdividef(hitn, hitd) : __fdividef(wn, wd);
}

// ---------------------------------------------------------------------------
// Kernel 1: two S=768 attentions via node eval + interpolation, + sentence
// copy. grid (32, 3), block 512.
// ---------------------------------------------------------------------------
__global__ void __launch_bounds__(512) attn_pre_interp(const float* __restrict__ sent,
                                                       const float* __restrict__ ts,
                                                       const float* __restrict__ oth,
                                                       const float* __restrict__ sd,
                                                       const float* __restrict__ ss) {
    const int b = blockIdx.x, task = blockIdx.y;
    const int tid = threadIdx.x, lane = tid & 31, wid = tid >> 5;

    if (task == 2) {
        for (int i = tid; i < 768; i += 512) g_fused[b * 2304 + i] = sent[b * 768 + i];
        return;
    }

    const float* q = (task == 0) ? oth : ss;
    const float* k = (task == 0) ? ts  : ss;
    const float* v = (task == 0) ? ts  : sd;
    const int outoff = (task == 0) ? 1536 : 768;

    __shared__ __align__(16) float sq[768], sk[768], sv[768];
    __shared__ float snum[NODES], sden[NODES];
    __shared__ float red[32];

    for (int i = tid; i < 768; i += 512) {
        sq[i] = q[b * 768 + i];
        sk[i] = k[b * 768 + i];
        sv[i] = v[b * 768 + i];
    }
    __syncthreads();

    float lmin = 1e30f, lmax = -1e30f;
    for (int i = tid; i < 768; i += 512) {
        float x = sq[i];
        lmin = fminf(lmin, x); lmax = fmaxf(lmax, x);
    }
#pragma unroll
    for (int o = 16; o > 0; o >>= 1) {
        lmin = fminf(lmin, __shfl_xor_sync(0xffffffffu, lmin, o));
        lmax = fmaxf(lmax, __shfl_xor_sync(0xffffffffu, lmax, o));
    }
    if (lane == 0) { red[wid] = lmin; red[16 + wid] = lmax; }
    __syncthreads();
    float xmin = red[0], xmax = red[16];
#pragma unroll
    for (int i = 1; i < 16; i++) { xmin = fminf(xmin, red[i]); xmax = fmaxf(xmax, red[16 + i]); }

    const float w  = (xmax - xmin) * (1.f / NI);
    const float hw = 0.5f * w;

    for (int m = wid; m < NODES; m += 16) {
        const int c = m / NNODE, mm = m - c * NNODE;
        const float Xl = (xmin + (c + 0.5f) * w + hw * CHEB[mm]) * LOG2E;
        float sn = 0.f, sd_ = 0.f;
#pragma unroll 4
        for (int t = lane; t < 768; t += 32) {
            float e = ex2f(Xl * sk[t]);
            sd_ += e;
            sn = fmaf(e, sv[t], sn);
        }
        sn = wredsum(sn); sd_ = wredsum(sd_);
        if (lane == 0) { snum[m] = sn; sden[m] = sd_; }
    }
    __syncthreads();

    const float invw = __fdividef(1.f, w);
    for (int s = tid; s < 768; s += 512)
        g_fused[b * 2304 + outoff + s] = interp_s(sq[s], xmin, w, hw, invw, snum, sden);
}

// ---------------------------------------------------------------------------
// Kernel 2 (fat): fused node table + shared projections.
// blocks [0,288): node eval — 1 node per warp (8 per block).
// blocks [288,432): proj split-K.
// ---------------------------------------------------------------------------
__global__ void __launch_bounds__(256) fat_kernel(const float* __restrict__ sent,
                                                  const float* __restrict__ Wsh) {
    const int bx = blockIdx.x;
    const int tid = threadIdx.x, lane = tid & 31, wid = tid >> 5;

    if (bx < FAT_NODE_BLOCKS) {
        const int b = bx & 31, grp = bx >> 5;     // grp 0..8, 8 nodes each

        __shared__ __align__(16) float sf[2304];
        __shared__ float red[16];

        for (int i = tid; i < 576; i += 256)
            *reinterpret_cast<float4*>(sf + i * 4) =
                *reinterpret_cast<const float4*>(g_fused + b * 2304 + i * 4);
        __syncthreads();

        float lmin = 1e30f, lmax = -1e30f;
        for (int i = tid; i < 2304; i += 256) {
            float x = sf[i];
            lmin = fminf(lmin, x); lmax = fmaxf(lmax, x);
        }
#pragma unroll
        for (int o = 16; o > 0; o >>= 1) {
            lmin = fminf(lmin, __shfl_xor_sync(0xffffffffu, lmin, o));
            lmax = fmaxf(lmax, __shfl_xor_sync(0xffffffffu, lmax, o));
        }
        if (lane == 0) { red[wid] = lmin; red[8 + wid] = lmax; }
        __syncthreads();
        float xmin = red[0], xmax = red[8];
#pragma unroll
        for (int i = 1; i < 8; i++) { xmin = fminf(xmin, red[i]); xmax = fmaxf(xmax, red[8 + i]); }

        if (grp == 0 && tid == 0) { g_frange[b * 2] = xmin; g_frange[b * 2 + 1] = xmax; }

        const float w  = (xmax - xmin) * (1.f / NI);
        const float hw = 0.5f * w;
        const int m = grp * 8 + wid;              // one node per warp

        const int c = m / NNODE, mm = m - c * NNODE;
        const float Xl = (xmin + (c + 0.5f) * w + hw * CHEB[mm]) * LOG2E;
        float sn = 0.f, sd_ = 0.f;
#pragma unroll 4
        for (int t = lane; t < 2304; t += 32) {
            float f = sf[t];
            float e = ex2f(Xl * f);
            sd_ += e;
            sn = fmaf(e, f, sn);                  // v == f
        }
        sn = wredsum(sn); sd_ = wredsum(sd_);
        if (lane == 0) g_nodes[b * NODES + m] = make_float2(sn, sd_);
        return;
    }

    // ----- proj section -----
    const int p    = bx - FAT_NODE_BLOCKS;
    const int task = p / (PROJ_KC * 2);
    const int rem  = p - task * PROJ_KC * 2;
    const int kc   = rem >> 1;
    const int jt   = rem & 1;
    const int j    = jt * 256 + tid;       // 0..511
    const int i0   = kc * PROJ_KCH;

    __shared__ __align__(16) float xs[PROJ_KCH][36];

    for (int e = tid; e < PROJ_KCH * 32; e += 256) {
        int i = e & 31, b = e >> 5;
        xs[i][b] = (task == 0) ? sent[b * 768 + i0 + i]
                               : g_fused[b * 2304 + 768 * task + i0 + i];
    }
    __syncthreads();

    float acc[32];
#pragma unroll
    for (int b = 0; b < 32; b++) acc[b] = 0.f;

#pragma unroll
    for (int i = 0; i < PROJ_KCH; i++) {
        float wv = Wsh[(i0 + i) * 512 + j];
#pragma unroll
        for (int b4 = 0; b4 < 8; b4++) {
            float4 x = *reinterpret_cast<const float4*>(&xs[i][b4 * 4]);
            acc[b4 * 4 + 0] = fmaf(x.x, wv, acc[b4 * 4 + 0]);
            acc[b4 * 4 + 1] = fmaf(x.y, wv, acc[b4 * 4 + 1]);
            acc[b4 * 4 + 2] = fmaf(x.z, wv, acc[b4 * 4 + 2]);
            acc[b4 * 4 + 3] = fmaf(x.w, wv, acc[b4 * 4 + 3]);
        }
    }

#pragma unroll
    for (int b = 0; b < 32; b++)
        g_pp[(((size_t)task * PROJ_KC + kc) * 32 + b) * 512 + j] = acc[b];
}

// ---------------------------------------------------------------------------
// Kernel 3: mlp1 with fused assemble. grid MLP_KC (120), block 256.
// ---------------------------------------------------------------------------
__global__ void __launch_bounds__(256) mlp1_fused(const float* __restrict__ W1,
                                                  const float* __restrict__ bsh) {
    const int kc = blockIdx.x;
    const int i0 = kc * MLP_KCH;
    const int j  = threadIdx.x;

    __shared__ __align__(16) float xs[MLP_KCH][36];

    if (kc < 72) {
        for (int e = threadIdx.x; e < MLP_KCH * 32; e += 256) {
            int ii = e & 31, b = e >> 5;
            const float xmin = g_frange[b * 2], xmax = g_frange[b * 2 + 1];
            const float w  = (xmax - xmin) * (1.f / NI);
            const float hw = 0.5f * w;
            const float invw = __fdividef(1.f, w);
            const float x = g_fused[b * 2304 + i0 + ii];
            xs[ii][b] = interp_g(x, xmin, w, hw, invw, g_nodes + b * NODES);
        }
    } else {
        const int t0   = i0 - 2304;
        const int task = t0 >> 9;
        const int jj0  = t0 & 511;
        for (int e = threadIdx.x; e < MLP_KCH * 32; e += 256) {
            int jl = e & 31, b = e >> 5;
            const int jj = jj0 + jl;
            float a = bsh[jj];
            const float* pp = g_pp + (((size_t)task * PROJ_KC) * 32 + b) * 512 + jj;
#pragma unroll
            for (int s = 0; s < PROJ_KC; s++) a += pp[(size_t)s * 32 * 512];
            xs[jl][b] = a;
        }
    }
    __syncthreads();

    float acc[32];
#pragma unroll
    for (int b = 0; b < 32; b++) acc[b] = 0.f;

#pragma unroll
    for (int i = 0; i < MLP_KCH; i++) {
        float w = W1[(i0 + i) * 256 + j];
#pragma unroll
        for (int b4 = 0; b4 < 8; b4++) {
            float4 x = *reinterpret_cast<const float4*>(&xs[i][b4 * 4]);
            acc[b4 * 4 + 0] = fmaf(x.x, w, acc[b4 * 4 + 0]);
            acc[b4 * 4 + 1] = fmaf(x.y, w, acc[b4 * 4 + 1]);
            acc[b4 * 4 + 2] = fmaf(x.z, w, acc[b4 * 4 + 2]);
            acc[b4 * 4 + 3] = fmaf(x.w, w, acc[b4 * 4 + 3]);
        }
    }

#pragma unroll
    for (int b = 0; b < 32; b++)
        g_h_part[((size_t)kc * 32 + b) * 256 + j] = acc[b];
}

// ---------------------------------------------------------------------------
// Kernel 4: tail with float4 16-way reduce. grid 32, block 1024.
// ---------------------------------------------------------------------------
__global__ void __launch_bounds__(1024) mlp_tail(const float* __restrict__ b1,
                                                 const float* __restrict__ W2,
                                                 const float* __restrict__ b2,
                                                 float* __restrict__ out) {
    const int b  = blockIdx.x;
    const int j4 = threadIdx.x & 63;          // float4 column 0..63
    const int qt = threadIdx.x >> 6;          // kc-group 0..15

    __shared__ __align__(16) float4 sred[16][64];
    __shared__ __align__(16) float h[256];

    const float4* src = reinterpret_cast<const float4*>(g_h_part);
    float4 a = make_float4(0.f, 0.f, 0.f, 0.f);
    const int ns = (qt < 8) ? 8 : 7;
#pragma unroll 8
    for (int s = 0; s < 8; s++) {
        if (s < ns) {
            const int kc = qt + 16 * s;
            float4 p = src[((size_t)kc * 32 + b) * 64 + j4];
            a.x += p.x; a.y += p.y; a.z += p.z; a.w += p.w;
        }
    }
    sred[qt][j4] = a;
    __syncthreads();

    if (threadIdx.x < 64) {
        float4 t = sred[0][threadIdx.x];
#pragma unroll
        for (int s = 1; s < 16; s++) {
            float4 p = sred[s][threadIdx.x];
            t.x += p.x; t.y += p.y; t.z += p.z; t.w += p.w;
        }
        float4 bb = reinterpret_cast<const float4*>(b1)[threadIdx.x];
        float4 hv;
        hv.x = fmaxf(t.x + bb.x, 0.f);
        hv.y = fmaxf(t.y + bb.y, 0.f);
        hv.z = fmaxf(t.z + bb.z, 0.f);
        hv.w = fmaxf(t.w + bb.w, 0.f);
        *reinterpret_cast<float4*>(h + threadIdx.x * 4) = hv;
    }
    __syncthreads();

    const int w = threadIdx.x >> 5, lane = threadIdx.x & 31;
    if (w < 7) {
        float s = 0.f;
#pragma unroll
        for (int q = 0; q < 8; q++)
            s = fmaf(h[q * 32 + lane], W2[(q * 32 + lane) * 7 + w], s);
#pragma unroll
        for (int o = 16; o > 0; o >>= 1) s += __shfl_xor_sync(0xffffffffu, s, o);
        if (lane == 0) out[b * 7 + w] = 1.f / (1.f + __expf(-(s + b2[w])));
    }
}

extern "C" void kernel_launch(void* const* d_in, const int* in_sizes, int n_in,
                              void* d_out, int out_size) {
    const float* sent = (const float*)d_in[0];
    const float* ts   = (const float*)d_in[1];
    const float* oth  = (const float*)d_in[2];
    const float* sd   = (const float*)d_in[3];
    const float* ss   = (const float*)d_in[4];
    const float* Wsh  = (const float*)d_in[5];
    const float* bsh  = (const float*)d_in[6];
    const float* W1   = (const float*)d_in[7];
    const float* b1   = (const float*)d_in[8];
    const float* W2   = (const float*)d_in[9];
    const float* b2   = (const float*)d_in[10];
    float* out = (float*)d_out;

    attn_pre_interp<<<dim3(32, 3), 512>>>(sent, ts, oth, sd, ss);
    fat_kernel<<<FAT_NODE_BLOCKS + FAT_PROJ_BLOCKS, 256>>>(sent, Wsh);
    mlp1_fused<<<MLP_KC, 256>>>(W1, bsh);
    mlp_tail<<<32, 1024>>>(b1, W2, b2, out);
}

// round 16
// speedup vs baseline: 1.2173x; 1.0903x over previous
#include <cuda_runtime.h>

#define LOG2E 1.4426950408889634f
#define NI 6                  // intervals per attention
#define NNODE 9               // Chebyshev nodes per interval (degree 8)
#define NODES (NI * NNODE)    // 54

#define PROJ_KC 24            // 768 / 32
#define PROJ_KCH 32
#define MLP_KC 120            // 3840 / 32
#define MLP_KCH 32

#define FAT_NODE_BLOCKS (NI * 32)              // 192 (block = one interval of one b)
#define FAT_PROJ_BLOCKS (PROJ_KC * 2 * 2)      // 96  (tasks 1,2)

// ---------------- scratch (__device__ globals; allocation-free rule) -------
__device__ float  g_fused[32 * 2304];            // [sentence | scene | speaker]
__device__ float  g_h_part[MLP_KC * 32 * 256];   // mlp1 partials [kc][b][j]
__device__ float  g_pp[3 * PROJ_KC * 32 * 512];  // proj partials [task][kc][b][j]
__device__ float2 g_nodes[32 * NODES];           // fused node table [b][m] (num,den)
__device__ float  g_frange[32 * 2];              // fused range [b][min,max]

__constant__ float CHEB[9] = {1.f, 0.92387953f, 0.70710678f, 0.38268343f, 0.f,
                              -0.38268343f, -0.70710678f, -0.92387953f, -1.f};
__constant__ float LAMB[9] = {0.5f, -1.f, 1.f, -1.f, 1.f, -1.f, 1.f, -1.f, 0.5f};

__device__ __forceinline__ float ex2f(float x) {
    float y; asm("ex2.approx.f32 %0, %1;" : "=f"(y) : "f"(x)); return y;
}
__device__ __forceinline__ float wredsum(float v) {
#pragma unroll
    for (int o = 16; o > 0; o >>= 1) v += __shfl_xor_sync(0xffffffffu, v, o);
    return v;
}

__device__ __forceinline__ float interp_s(float x, float xmin, float w, float hw,
                                          float invw,
                                          const float* __restrict__ snum,
                                          const float* __restrict__ sden) {
    int c = (int)((x - xmin) * invw);
    c = (c < 0) ? 0 : ((c >= NI) ? NI - 1 : c);
    const float x0 = xmin + (c + 0.5f) * w;
    const int base = c * NNODE;
    float wn = 0.f, wd = 0.f, hitn = 0.f, hitd = 1.f;
    bool hit = false;
#pragma unroll
    for (int m = 0; m < NNODE; m++) {
        float d = x - (x0 + hw * CHEB[m]);
        if (fabsf(d) < 1e-10f) { hit = true; hitn = snum[base + m]; hitd = sden[base + m]; d = 1.f; }
        float wm = __fdividef(LAMB[m], d);
        wn = fmaf(wm, snum[base + m], wn);
        wd = fmaf(wm, sden[base + m], wd);
    }
    return hit ? __fdividef(hitn, hitd) : __fdividef(wn, wd);
}

__device__ __forceinline__ float interp_g(float x, float xmin, float w, float hw,
                                          float invw,
                                          const float2* __restrict__ nodes) {
    int c = (int)((x - xmin) * invw);
    c = (c < 0) ? 0 : ((c >= NI) ? NI - 1 : c);
    const float x0 = xmin + (c + 0.5f) * w;
    const float2* nb = nodes + c * NNODE;
    float wn = 0.f, wd = 0.f, hitn = 0.f, hitd = 1.f;
    bool hit = false;
#pragma unroll
    for (int m = 0; m < NNODE; m++) {
        float2 nd = nb[m];
        float d = x - (x0 + hw * CHEB[m]);
        if (fabsf(d) < 1e-10f) { hit = true; hitn = nd.x; hitd = nd.y; d = 1.f; }
        float wm = __fdividef(LAMB[m], d);
        wn = fmaf(wm, nd.x, wn);
        wd = fmaf(wm, nd.y, wd);
    }
    return hit ? __fdividef(hitn, hitd) : __fdividef(wn, wd);
}

// ---------------------------------------------------------------------------
// Kernel 1: grid 120, block 512.
// bx<64: heavy pre-attention (b, task).  64<=bx<96: sentence copy.
// bx>=96: proj task 0 (kc = bx-96; independent of attention outputs).
// ---------------------------------------------------------------------------
__global__ void __launch_bounds__(512) attn_pre_interp(const float* __restrict__ sent,
                                                       const float* __restrict__ ts,
                                                       const float* __restrict__ oth,
                                                       const float* __restrict__ sd,
                                                       const float* __restrict__ ss,
                                                       const float* __restrict__ Wsh) {
    const int bx = blockIdx.x;
    const int tid = threadIdx.x, lane = tid & 31, wid = tid >> 5;

    __shared__ __align__(16) union SM {
        struct { float sq[768], sk[768], sv[768], snum[NODES], sden[NODES], red[32]; } h;
        struct { float xs[PROJ_KCH][36]; } p;
    } sm;

    if (bx >= 96) {
        // ---- proj task 0: one kc per block, j = tid (0..511) ----
        const int kc = bx - 96, i0 = kc * PROJ_KCH, j = tid;
        for (int e = tid; e < PROJ_KCH * 32; e += 512) {
            int i = e & 31, b = e >> 5;
            sm.p.xs[i][b] = sent[b * 768 + i0 + i];
        }
        __syncthreads();
        float acc[32];
#pragma unroll
        for (int b = 0; b < 32; b++) acc[b] = 0.f;
#pragma unroll
        for (int i = 0; i < PROJ_KCH; i++) {
            float wv = Wsh[(i0 + i) * 512 + j];
#pragma unroll
            for (int b4 = 0; b4 < 8; b4++) {
                float4 x = *reinterpret_cast<const float4*>(&sm.p.xs[i][b4 * 4]);
                acc[b4 * 4 + 0] = fmaf(x.x, wv, acc[b4 * 4 + 0]);
                acc[b4 * 4 + 1] = fmaf(x.y, wv, acc[b4 * 4 + 1]);
                acc[b4 * 4 + 2] = fmaf(x.z, wv, acc[b4 * 4 + 2]);
                acc[b4 * 4 + 3] = fmaf(x.w, wv, acc[b4 * 4 + 3]);
            }
        }
#pragma unroll
        for (int b = 0; b < 32; b++)
            g_pp[((size_t)kc * 32 + b) * 512 + j] = acc[b];
        return;
    }

    if (bx >= 64) {
        const int b = bx - 64;
        for (int i = tid; i < 768; i += 512) g_fused[b * 2304 + i] = sent[b * 768 + i];
        return;
    }

    // ---- heavy pre-attention ----
    const int b = bx & 31, task = bx >> 5;
    const float* q = (task == 0) ? oth : ss;
    const float* k = (task == 0) ? ts  : ss;
    const float* v = (task == 0) ? ts  : sd;
    const int outoff = (task == 0) ? 1536 : 768;

    for (int i = tid; i < 768; i += 512) {
        sm.h.sq[i] = q[b * 768 + i];
        sm.h.sk[i] = k[b * 768 + i];
        sm.h.sv[i] = v[b * 768 + i];
    }
    __syncthreads();

    float lmin = 1e30f, lmax = -1e30f;
    for (int i = tid; i < 768; i += 512) {
        float x = sm.h.sq[i];
        lmin = fminf(lmin, x); lmax = fmaxf(lmax, x);
    }
#pragma unroll
    for (int o = 16; o > 0; o >>= 1) {
        lmin = fminf(lmin, __shfl_xor_sync(0xffffffffu, lmin, o));
        lmax = fmaxf(lmax, __shfl_xor_sync(0xffffffffu, lmax, o));
    }
    if (lane == 0) { sm.h.red[wid] = lmin; sm.h.red[16 + wid] = lmax; }
    __syncthreads();
    float xmin = sm.h.red[0], xmax = sm.h.red[16];
#pragma unroll
    for (int i = 1; i < 16; i++) {
        xmin = fminf(xmin, sm.h.red[i]); xmax = fmaxf(xmax, sm.h.red[16 + i]);
    }

    const float w  = (xmax - xmin) * (1.f / NI);
    const float hw = 0.5f * w;

    for (int m = wid; m < NODES; m += 16) {
        const int c = m / NNODE, mm = m - c * NNODE;
        const float Xl = (xmin + (c + 0.5f) * w + hw * CHEB[mm]) * LOG2E;
        float sn = 0.f, sd_ = 0.f;
#pragma unroll 4
        for (int t = lane; t < 768; t += 32) {
            float e = ex2f(Xl * sm.h.sk[t]);
            sd_ += e;
            sn = fmaf(e, sm.h.sv[t], sn);
        }
        sn = wredsum(sn); sd_ = wredsum(sd_);
        if (lane == 0) { sm.h.snum[m] = sn; sm.h.sden[m] = sd_; }
    }
    __syncthreads();

    const float invw = __fdividef(1.f, w);
    for (int s = tid; s < 768; s += 512)
        g_fused[b * 2304 + outoff + s] =
            interp_s(sm.h.sq[s], xmin, w, hw, invw, sm.h.snum, sm.h.sden);
}

// ---------------------------------------------------------------------------
// Kernel 2 (fat): grid 288, block 288 (9 warps).
// bx<192: node eval — block = (b, interval grp), 1 node per warp.
// bx>=192: proj tasks 1,2 (compute guarded to tid<256).
// ---------------------------------------------------------------------------
__global__ void __launch_bounds__(288) fat_kernel(const float* __restrict__ Wsh) {
    const int bx = blockIdx.x;
    const int tid = threadIdx.x, lane = tid & 31, wid = tid >> 5;

    __shared__ __align__(16) union SM {
        struct { float sf[2304], red[32]; } n;
        struct { float xs[PROJ_KCH][36]; } p;
    } sm;

    if (bx < FAT_NODE_BLOCKS) {
        const int b = bx & 31, grp = bx >> 5;     // grp 0..5 (interval)

        for (int i = tid; i < 576; i += 288)
            *reinterpret_cast<float4*>(sm.n.sf + i * 4) =
                *reinterpret_cast<const float4*>(g_fused + b * 2304 + i * 4);
        __syncthreads();

        float lmin = 1e30f, lmax = -1e30f;
        for (int i = tid; i < 2304; i += 288) {
            float x = sm.n.sf[i];
            lmin = fminf(lmin, x); lmax = fmaxf(lmax, x);
        }
#pragma unroll
        for (int o = 16; o > 0; o >>= 1) {
            lmin = fminf(lmin, __shfl_xor_sync(0xffffffffu, lmin, o));
            lmax = fmaxf(lmax, __shfl_xor_sync(0xffffffffu, lmax, o));
        }
        if (lane == 0) { sm.n.red[wid] = lmin; sm.n.red[16 + wid] = lmax; }
        __syncthreads();
        float xmin = sm.n.red[0], xmax = sm.n.red[16];
#pragma unroll
        for (int i = 1; i < 9; i++) {
            xmin = fminf(xmin, sm.n.red[i]); xmax = fmaxf(xmax, sm.n.red[16 + i]);
        }

        if (grp == 0 && tid == 0) { g_frange[b * 2] = xmin; g_frange[b * 2 + 1] = xmax; }

        const float w  = (xmax - xmin) * (1.f / NI);
        const float hw = 0.5f * w;
        const int m = grp * NNODE + wid;          // one node per warp (wid 0..8)

        const float Xl = (xmin + (grp + 0.5f) * w + hw * CHEB[wid]) * LOG2E;
        float sn = 0.f, sd_ = 0.f;
#pragma unroll 4
        for (int t = lane; t < 2304; t += 32) {
            float f = sm.n.sf[t];
            float e = ex2f(Xl * f);
            sd_ += e;
            sn = fmaf(e, f, sn);                  // v == f
        }
        sn = wredsum(sn); sd_ = wredsum(sd_);
        if (lane == 0) g_nodes[b * NODES + m] = make_float2(sn, sd_);
        return;
    }

    // ----- proj tasks 1, 2 -----
    const int p    = bx - FAT_NODE_BLOCKS;        // 0..95
    const int task = 1 + p / (PROJ_KC * 2);
    const int rem  = p % (PROJ_KC * 2);
    const int kc   = rem >> 1;
    const int jt   = rem & 1;
    const int i0   = kc * PROJ_KCH;

    for (int e = tid; e < PROJ_KCH * 32; e += 288) {
        int i = e & 31, b = e >> 5;
        sm.p.xs[i][b] = g_fused[b * 2304 + 768 * task + i0 + i];
    }
    __syncthreads();

    if (tid < 256) {
        const int j = jt * 256 + tid;             // 0..511
        float acc[32];
#pragma unroll
        for (int b = 0; b < 32; b++) acc[b] = 0.f;
#pragma unroll
        for (int i = 0; i < PROJ_KCH; i++) {
            float wv = Wsh[(i0 + i) * 512 + j];
#pragma unroll
            for (int b4 = 0; b4 < 8; b4++) {
                float4 x = *reinterpret_cast<const float4*>(&sm.p.xs[i][b4 * 4]);
                acc[b4 * 4 + 0] = fmaf(x.x, wv, acc[b4 * 4 + 0]);
                acc[b4 * 4 + 1] = fmaf(x.y, wv, acc[b4 * 4 + 1]);
                acc[b4 * 4 + 2] = fmaf(x.z, wv, acc[b4 * 4 + 2]);
                acc[b4 * 4 + 3] = fmaf(x.w, wv, acc[b4 * 4 + 3]);
            }
        }
#pragma unroll
        for (int b = 0; b < 32; b++)
            g_pp[(((size_t)task * PROJ_KC + kc) * 32 + b) * 512 + j] = acc[b];
    }
}

// ---------------------------------------------------------------------------
// Kernel 3: mlp1 with fused assemble. grid MLP_KC (120), block 256.
// ---------------------------------------------------------------------------
__global__ void __launch_bounds__(256) mlp1_fused(const float* __restrict__ W1,
                                                  const float* __restrict__ bsh) {
    const int kc = blockIdx.x;
    const int i0 = kc * MLP_KCH;
    const int j  = threadIdx.x;

    __shared__ __align__(16) float xs[MLP_KCH][36];

    if (kc < 72) {
        for (int e = threadIdx.x; e < MLP_KCH * 32; e += 256) {
            int ii = e & 31, b = e >> 5;
            const float xmin = g_frange[b * 2], xmax = g_frange[b * 2 + 1];
            const float w  = (xmax - xmin) * (1.f / NI);
            const float hw = 0.5f * w;
            const float invw = __fdividef(1.f, w);
            const float x = g_fused[b * 2304 + i0 + ii];
            xs[ii][b] = interp_g(x, xmin, w, hw, invw, g_nodes + b * NODES);
        }
    } else {
        const int t0   = i0 - 2304;
        const int task = t0 >> 9;
        const int jj0  = t0 & 511;
        for (int e = threadIdx.x; e < MLP_KCH * 32; e += 256) {
            int jl = e & 31, b = e >> 5;
            const int jj = jj0 + jl;
            float a = bsh[jj];
            const float* pp = g_pp + (((size_t)task * PROJ_KC) * 32 + b) * 512 + jj;
#pragma unroll
            for (int s = 0; s < PROJ_KC; s++) a += pp[(size_t)s * 32 * 512];
            xs[jl][b] = a;
        }
    }
    __syncthreads();

    float acc[32];
#pragma unroll
    for (int b = 0; b < 32; b++) acc[b] = 0.f;

#pragma unroll
    for (int i = 0; i < MLP_KCH; i++) {
        float w = W1[(i0 + i) * 256 + j];
#pragma unroll
        for (int b4 = 0; b4 < 8; b4++) {
            float4 x = *reinterpret_cast<const float4*>(&xs[i][b4 * 4]);
            acc[b4 * 4 + 0] = fmaf(x.x, w, acc[b4 * 4 + 0]);
            acc[b4 * 4 + 1] = fmaf(x.y, w, acc[b4 * 4 + 1]);
            acc[b4 * 4 + 2] = fmaf(x.z, w, acc[b4 * 4 + 2]);
            acc[b4 * 4 + 3] = fmaf(x.w, w, acc[b4 * 4 + 3]);
        }
    }

#pragma unroll
    for (int b = 0; b < 32; b++)
        g_h_part[((size_t)kc * 32 + b) * 256 + j] = acc[b];
}

// ---------------------------------------------------------------------------
// Kernel 4: tail with float4 16-way reduce. grid 32, block 1024.
// ---------------------------------------------------------------------------
__global__ void __launch_bounds__(1024) mlp_tail(const float* __restrict__ b1,
                                                 const float* __restrict__ W2,
                                                 const float* __restrict__ b2,
                                                 float* __restrict__ out) {
    const int b  = blockIdx.x;
    const int j4 = threadIdx.x & 63;          // float4 column 0..63
    const int qt = threadIdx.x >> 6;          // kc-group 0..15

    __shared__ __align__(16) float4 sred[16][64];
    __shared__ __align__(16) float h[256];

    const float4* src = reinterpret_cast<const float4*>(g_h_part);
    float4 a = make_float4(0.f, 0.f, 0.f, 0.f);
    const int ns = (qt < 8) ? 8 : 7;
#pragma unroll 8
    for (int s = 0; s < 8; s++) {
        if (s < ns) {
            const int kc = qt + 16 * s;
            float4 p = src[((size_t)kc * 32 + b) * 64 + j4];
            a.x += p.x; a.y += p.y; a.z += p.z; a.w += p.w;
        }
    }
    sred[qt][j4] = a;
    __syncthreads();

    if (threadIdx.x < 64) {
        float4 t = sred[0][threadIdx.x];
#pragma unroll
        for (int s = 1; s < 16; s++) {
            float4 p = sred[s][threadIdx.x];
            t.x += p.x; t.y += p.y; t.z += p.z; t.w += p.w;
        }
        float4 bb = reinterpret_cast<const float4*>(b1)[threadIdx.x];
        float4 hv;
        hv.x = fmaxf(t.x + bb.x, 0.f);
        hv.y = fmaxf(t.y + bb.y, 0.f);
        hv.z = fmaxf(t.z + bb.z, 0.f);
        hv.w = fmaxf(t.w + bb.w, 0.f);
        *reinterpret_cast<float4*>(h + threadIdx.x * 4) = hv;
    }
    __syncthreads();

    const int w = threadIdx.x >> 5, lane = threadIdx.x & 31;
    if (w < 7) {
        float s = 0.f;
#pragma unroll
        for (int q = 0; q < 8; q++)
            s = fmaf(h[q * 32 + lane], W2[(q * 32 + lane) * 7 + w], s);
#pragma unroll
        for (int o = 16; o > 0; o >>= 1) s += __shfl_xor_sync(0xffffffffu, s, o);
        if (lane == 0) out[b * 7 + w] = 1.f / (1.f + __expf(-(s + b2[w])));
    }
}

extern "C" void kernel_launch(void* const* d_in, const int* in_sizes, int n_in,
                              void* d_out, int out_size) {
    const float* sent = (const float*)d_in[0];
    const float* ts   = (const float*)d_in[1];
    const float* oth  = (const float*)d_in[2];
    const float* sd   = (const float*)d_in[3];
    const float* ss   = (const float*)d_in[4];
    const float* Wsh  = (const float*)d_in[5];
    const float* bsh  = (const float*)d_in[6];
    const float* W1   = (const float*)d_in[7];
    const float* b1   = (const float*)d_in[8];
    const float* W2   = (const float*)d_in[9];
    const float* b2   = (const float*)d_in[10];
    float* out = (float*)d_out;

    attn_pre_interp<<<120, 512>>>(sent, ts, oth, sd, ss, Wsh);
    fat_kernel<<<FAT_NODE_BLOCKS + FAT_PROJ_BLOCKS, 288>>>(Wsh);
    mlp1_fused<<<MLP_KC, 256>>>(W1, bsh);
    mlp_tail<<<32, 1024>>>(b1, W2, b2, out);
}